// round 13
// baseline (speedup 1.0000x reference)
#include <cuda_runtime.h>

#define TT 1024
#define OO 512
#define DD 256
#define HH 512

__device__ float g_ht[TT * HH];   // z_t @ W1[:D]            [1024,512]
__device__ float g_ho[OO * HH];   // z_o @ W1[D:] + b1       [512,512]
__device__ float g_ct[TT];        // 0.505 * <ht[t], W2>
__device__ float g_co[OO];        // 0.505 * <ho[o], W2> + b2

typedef unsigned long long u64;

__device__ __forceinline__ u64 add2(u64 a, u64 b) {
    u64 d; asm("add.rn.f32x2 %0,%1,%2;" : "=l"(d) : "l"(a), "l"(b)); return d;
}
__device__ __forceinline__ u64 fma2(u64 a, u64 b, u64 c) {
    u64 d; asm("fma.rn.f32x2 %0,%1,%2,%3;" : "=l"(d) : "l"(a), "l"(b), "l"(c)); return d;
}
__device__ __forceinline__ u64 dup2(float v) {
    u64 d; asm("mov.b64 %0,{%1,%1};" : "=l"(d) : "f"(v)); return d;
}

// ---------------------------------------------------------------------------
// Fused GEMM over combined M=1536: rows [0,1024)=z_t@W1[:D],
// [1024,1536)=z_o@W1[D:]+b1.
// BM=64, BN=64, BK=32, 128 threads, micro 4m x 8n:
// per k = 1 LDS.128(a) + 2 LDS.128(b) + 4 dup + 16 FFMA2 (0.75 wf/FFMA2).
// Grid (8 n-tiles, 24 m-tiles) = 192 CTAs, all resident in one wave.
// Double-buffered smem, 1 syncthreads per 32-k block.
// ---------------------------------------------------------------------------
__global__ __launch_bounds__(128) void gemm_kernel(
    const float* __restrict__ z_t, const float* __restrict__ z_o,
    const float* __restrict__ W1,  const float* __restrict__ b1)
{
    __shared__ float As[2][32][68];   // [buf][k][m]; 272B row (16B mult)
    __shared__ float Bs[2][32][68];   // [buf][k][n]; 272B row (16B mult)

    const int tid = threadIdx.x;
    const int mt  = blockIdx.y;             // 0..23
    const int n0  = blockIdx.x << 6;        // 0..448
    const bool isHo = (mt >= 16);
    const int m0 = (isHo ? (mt - 16) : mt) << 6;
    const float* A = isHo ? z_o : z_t;
    const float* B = isHo ? (W1 + (u64)DD * HH) : W1;
    float* C = isHo ? g_ho : g_ht;

    // A staging: m = tid&63, k-half = (tid>>6)*16, 4 float4 along k
    const int am  = tid & 63;
    const int akh = (tid >> 6) << 4;        // 0 or 16
    // B staging: k row = tid>>2 (0..31), n base = (tid&3)*16, 4 float4
    const int bk  = tid >> 2;
    const int bn4 = (tid & 3) << 4;

    // compute: n oct at tx*8, m quad at ty*4
    const int tx = tid & 7;
    const int ty = tid >> 3;                // 0..15

    u64 acc[4][4];                          // [m][n-pair]
    #pragma unroll
    for (int m = 0; m < 4; m++)
        #pragma unroll
        for (int j = 0; j < 4; j++) acc[m][j] = 0ull;

    const float* aptr = &A[(u64)(m0 + am) * DD + akh];
    const float* bptr = &B[(u64)bk * HH + n0 + bn4];

    float4 va[4], vb[4];

    // ---- prologue: stage 0 ----
    #pragma unroll
    for (int q = 0; q < 4; q++)
        va[q] = *reinterpret_cast<const float4*>(aptr + (q << 2));
    #pragma unroll
    for (int q = 0; q < 4; q++)
        vb[q] = *reinterpret_cast<const float4*>(bptr + (q << 2));

    #pragma unroll
    for (int q = 0; q < 4; q++) {
        As[0][akh + (q << 2) + 0][am] = va[q].x;
        As[0][akh + (q << 2) + 1][am] = va[q].y;
        As[0][akh + (q << 2) + 2][am] = va[q].z;
        As[0][akh + (q << 2) + 3][am] = va[q].w;
    }
    #pragma unroll
    for (int q = 0; q < 4; q++)
        *reinterpret_cast<float4*>(&Bs[0][bk][bn4 + (q << 2)]) = vb[q];
    __syncthreads();

    #pragma unroll 1
    for (int kb = 0; kb < 8; kb++) {
        const int cur = kb & 1, nxt = cur ^ 1;

        if (kb < 7) {   // next stage's global loads, hidden under compute
            const float* ap = aptr + ((kb + 1) << 5);
            #pragma unroll
            for (int q = 0; q < 4; q++)
                va[q] = *reinterpret_cast<const float4*>(ap + (q << 2));
            const float* bp = bptr + (u64)((kb + 1) << 5) * HH;
            #pragma unroll
            for (int q = 0; q < 4; q++)
                vb[q] = *reinterpret_cast<const float4*>(bp + (q << 2));
        }

        #pragma unroll
        for (int k = 0; k < 32; k++) {
            float4 af = *reinterpret_cast<const float4*>(&As[cur][k][ty << 2]);
            ulonglong2 b01 = *reinterpret_cast<const ulonglong2*>(&Bs[cur][k][tx << 3]);
            ulonglong2 b23 = *reinterpret_cast<const ulonglong2*>(&Bs[cur][k][(tx << 3) + 4]);
            u64 ad0 = dup2(af.x), ad1 = dup2(af.y), ad2 = dup2(af.z), ad3 = dup2(af.w);
            acc[0][0] = fma2(ad0, b01.x, acc[0][0]);
            acc[0][1] = fma2(ad0, b01.y, acc[0][1]);
            acc[0][2] = fma2(ad0, b23.x, acc[0][2]);
            acc[0][3] = fma2(ad0, b23.y, acc[0][3]);
            acc[1][0] = fma2(ad1, b01.x, acc[1][0]);
            acc[1][1] = fma2(ad1, b01.y, acc[1][1]);
            acc[1][2] = fma2(ad1, b23.x, acc[1][2]);
            acc[1][3] = fma2(ad1, b23.y, acc[1][3]);
            acc[2][0] = fma2(ad2, b01.x, acc[2][0]);
            acc[2][1] = fma2(ad2, b01.y, acc[2][1]);
            acc[2][2] = fma2(ad2, b23.x, acc[2][2]);
            acc[2][3] = fma2(ad2, b23.y, acc[2][3]);
            acc[3][0] = fma2(ad3, b01.x, acc[3][0]);
            acc[3][1] = fma2(ad3, b01.y, acc[3][1]);
            acc[3][2] = fma2(ad3, b23.x, acc[3][2]);
            acc[3][3] = fma2(ad3, b23.y, acc[3][3]);
        }

        if (kb < 7) {   // store into the other buffer, then sync
            #pragma unroll
            for (int q = 0; q < 4; q++) {
                As[nxt][akh + (q << 2) + 0][am] = va[q].x;
                As[nxt][akh + (q << 2) + 1][am] = va[q].y;
                As[nxt][akh + (q << 2) + 2][am] = va[q].z;
                As[nxt][akh + (q << 2) + 3][am] = va[q].w;
            }
            #pragma unroll
            for (int q = 0; q < 4; q++)
                *reinterpret_cast<float4*>(&Bs[nxt][bk][bn4 + (q << 2)]) = vb[q];
            __syncthreads();
        }
    }

    // epilogue: thread's n range contiguous: n0 + tx*8 .. +7
    float4 bvA = make_float4(0.f, 0.f, 0.f, 0.f);
    float4 bvB = make_float4(0.f, 0.f, 0.f, 0.f);
    if (isHo) {
        bvA = *reinterpret_cast<const float4*>(&b1[n0 + (tx << 3)]);
        bvB = *reinterpret_cast<const float4*>(&b1[n0 + (tx << 3) + 4]);
    }

    #pragma unroll
    for (int m = 0; m < 4; m++) {
        float2 p0 = *reinterpret_cast<float2*>(&acc[m][0]);
        float2 p1 = *reinterpret_cast<float2*>(&acc[m][1]);
        float2 p2 = *reinterpret_cast<float2*>(&acc[m][2]);
        float2 p3 = *reinterpret_cast<float2*>(&acc[m][3]);
        float4 r0 = make_float4(p0.x + bvA.x, p0.y + bvA.y, p1.x + bvA.z, p1.y + bvA.w);
        float4 r1 = make_float4(p2.x + bvB.x, p2.y + bvB.y, p3.x + bvB.z, p3.y + bvB.w);
        int r = m0 + (ty << 2) + m;
        *reinterpret_cast<float4*>(&C[(u64)r * HH + n0 + (tx << 3)])     = r0;
        *reinterpret_cast<float4*>(&C[(u64)r * HH + n0 + (tx << 3) + 4]) = r1;
    }
}

// ---------------------------------------------------------------------------
// Per-row linear terms: ct[t] = 0.505*<ht[t],W2>, co[o] = 0.505*<ho[o],W2>+b2
// ---------------------------------------------------------------------------
__global__ __launch_bounds__(256) void reduce_kernel(
    const float* __restrict__ W2, const float* __restrict__ b2)
{
    int warp = (blockIdx.x * blockDim.x + threadIdx.x) >> 5;
    int lane = threadIdx.x & 31;
    const float* row;
    float* dst;
    float extra = 0.f;
    if (warp < TT) { row = g_ht + (u64)warp * HH; dst = g_ct + warp; }
    else { row = g_ho + (u64)(warp - TT) * HH; dst = g_co + (warp - TT); extra = b2[0]; }
    float s = 0.f;
    #pragma unroll
    for (int i = 0; i < 4; i++) {
        float4 v = *reinterpret_cast<const float4*>(&row[(lane + 32 * i) << 2]);
        float4 w = *reinterpret_cast<const float4*>(&W2[(lane + 32 * i) << 2]);
        s += v.x * w.x + v.y * w.y + v.z * w.z + v.w * w.w;
    }
    #pragma unroll
    for (int off = 16; off; off >>= 1) s += __shfl_xor_sync(0xffffffffu, s, off);
    if (lane == 0) *dst = 0.505f * s + extra;
}

// ---------------------------------------------------------------------------
// Pairwise kernel: out[t,o] = ct[t]+co[o] + sum_h |ht+ho| * (0.495*W2[h])
// 64x64 tile, 256 threads, 128 CTAs, micro 4t x 4o (2.0 wf per output-hq —
// L1/fma/alu/issue all ~balanced). Depth-2 register pipeline over hq so the
// per-hq LDS latency is covered by the previous hq's 128-instr compute body.
// ---------------------------------------------------------------------------
__global__ __launch_bounds__(256) void pair_kernel(
    const float* __restrict__ W2, float* __restrict__ out)
{
    __shared__ float4 sA[16][65];      // [hq][t], float4 = 4 h
    __shared__ float4 sB[16][65];      // [hq][o]
    __shared__ float4 sW[HH / 4];      // 0.495*W2 quads

    const int tid = threadIdx.x;
    const int tx = tid & 15;           // o lane (o = tx + 16j)
    const int ty = tid >> 4;           // t lane (t = ty + 16i)
    const int t0 = blockIdx.y << 6;
    const int o0 = blockIdx.x << 6;

    if (tid < HH / 4) {
        float4 w = *reinterpret_cast<const float4*>(&W2[tid << 2]);
        w.x *= 0.495f; w.y *= 0.495f; w.z *= 0.495f; w.w *= 0.495f;
        sW[tid] = w;
    }

    u64 acc[4][4];
    #pragma unroll
    for (int i = 0; i < 4; i++)
        #pragma unroll
        for (int j = 0; j < 4; j++) acc[i][j] = 0ull;

    const int hs = tid & 15;           // hq for staging
    const int ts = tid >> 4;           // 0..15
    const u64 SMASK = 0x7fffffff7fffffffULL;

    const float* pa[4];
    const float* pb[4];
    #pragma unroll
    for (int r = 0; r < 4; r++) {
        pa[r] = &g_ht[(u64)(t0 + ts + (r << 4)) * HH + (hs << 2)];
        pb[r] = &g_ho[(u64)(o0 + ts + (r << 4)) * HH + (hs << 2)];
    }

    float4 va[4], vb[4];
    #pragma unroll
    for (int r = 0; r < 4; r++) {
        va[r] = *reinterpret_cast<const float4*>(pa[r]);
        vb[r] = *reinterpret_cast<const float4*>(pb[r]);
    }

    #pragma unroll 1
    for (int c = 0; c < 8; c++) {      // 8 chunks of 64 h
        __syncthreads();
        #pragma unroll
        for (int r = 0; r < 4; r++) {
            sA[hs][ts + (r << 4)] = va[r];
            sB[hs][ts + (r << 4)] = vb[r];
        }
        __syncthreads();

        if (c < 7) {                   // prefetch next chunk under compute
            int off = (c + 1) << 6;
            #pragma unroll
            for (int r = 0; r < 4; r++) {
                va[r] = *reinterpret_cast<const float4*>(pa[r] + off);
                vb[r] = *reinterpret_cast<const float4*>(pb[r] + off);
            }
        }

        // ---- depth-2 pipelined hq loop ----
        ulonglong2 w = *reinterpret_cast<const ulonglong2*>(&sW[c << 4]);
        ulonglong2 a[4], b[4];
        #pragma unroll
        for (int i = 0; i < 4; i++)
            a[i] = *reinterpret_cast<const ulonglong2*>(&sA[0][ty + (i << 4)]);
        #pragma unroll
        for (int j = 0; j < 4; j++)
            b[j] = *reinterpret_cast<const ulonglong2*>(&sB[0][tx + (j << 4)]);

        #pragma unroll
        for (int hq = 0; hq < 16; hq++) {
            ulonglong2 wn, an[4], bn[4];
            if (hq < 15) {
                wn = *reinterpret_cast<const ulonglong2*>(&sW[(c << 4) + hq + 1]);
                #pragma unroll
                for (int i = 0; i < 4; i++)
                    an[i] = *reinterpret_cast<const ulonglong2*>(&sA[hq + 1][ty + (i << 4)]);
                #pragma unroll
                for (int j = 0; j < 4; j++)
                    bn[j] = *reinterpret_cast<const ulonglong2*>(&sB[hq + 1][tx + (j << 4)]);
            }

            #pragma unroll
            for (int i = 0; i < 4; i++)
                #pragma unroll
                for (int j = 0; j < 4; j++) {
                    u64 x = add2(a[i].x, b[j].x) & SMASK;
                    acc[i][j] = fma2(x, w.x, acc[i][j]);
                    u64 y = add2(a[i].y, b[j].y) & SMASK;
                    acc[i][j] = fma2(y, w.y, acc[i][j]);
                }

            if (hq < 15) {
                w = wn;
                #pragma unroll
                for (int i = 0; i < 4; i++) a[i] = an[i];
                #pragma unroll
                for (int j = 0; j < 4; j++) b[j] = bn[j];
            }
        }
    }

    float ctv[4], cov[4];
    #pragma unroll
    for (int i = 0; i < 4; i++) ctv[i] = g_ct[t0 + ty + (i << 4)];
    #pragma unroll
    for (int j = 0; j < 4; j++) cov[j] = g_co[o0 + tx + (j << 4)];
    #pragma unroll
    for (int i = 0; i < 4; i++)
        #pragma unroll
        for (int j = 0; j < 4; j++) {
            float2 p = *reinterpret_cast<float2*>(&acc[i][j]);
            out[(u64)(t0 + ty + (i << 4)) * OO + o0 + tx + (j << 4)]
                = ctv[i] + cov[j] + p.x + p.y;
        }
}

extern "C" void kernel_launch(void* const* d_in, const int* in_sizes, int n_in,
                              void* d_out, int out_size)
{
    const float* z_t = (const float*)d_in[0];   // [1024,256]
    const float* z_o = (const float*)d_in[1];   // [512,256]
    const float* W1  = (const float*)d_in[2];   // [512,512]
    const float* b1  = (const float*)d_in[3];   // [512]
    const float* W2  = (const float*)d_in[4];   // [512,1]
    const float* b2  = (const float*)d_in[5];   // [1]
    float* out = (float*)d_out;                 // [1024,512]

    gemm_kernel<<<dim3(8, 24), 128>>>(z_t, z_o, W1, b1);
    reduce_kernel<<<192, 256>>>(W2, b2);
    pair_kernel<<<dim3(OO / 64, TT / 64), 256>>>(W2, out);
}

// round 14
// speedup vs baseline: 1.0315x; 1.0315x over previous
#include <cuda_runtime.h>

#define TT 1024
#define OO 512
#define DD 256
#define HH 512

__device__ float g_ht[TT * HH];   // z_t @ W1[:D]            [1024,512]
__device__ float g_ho[OO * HH];   // z_o @ W1[D:] + b1       [512,512]
__device__ float g_ct[TT];        // 0.505 * <ht[t], W2>
__device__ float g_co[OO];        // 0.505 * <ho[o], W2> + b2

typedef unsigned long long u64;

__device__ __forceinline__ u64 add2(u64 a, u64 b) {
    u64 d; asm("add.rn.f32x2 %0,%1,%2;" : "=l"(d) : "l"(a), "l"(b)); return d;
}
__device__ __forceinline__ u64 fma2(u64 a, u64 b, u64 c) {
    u64 d; asm("fma.rn.f32x2 %0,%1,%2,%3;" : "=l"(d) : "l"(a), "l"(b), "l"(c)); return d;
}
__device__ __forceinline__ u64 dup2(float v) {
    u64 d; asm("mov.b64 %0,{%1,%1};" : "=l"(d) : "f"(v)); return d;
}

// ---------------------------------------------------------------------------
// Fused GEMM over combined M=1536: rows [0,1024)=z_t@W1[:D],
// [1024,1536)=z_o@W1[D:]+b1.
// BM=64, BN=64, BK=16, 64 threads, micro 8m x 8n (crossbar/fma balanced:
// per warp-k 4 LDS.128 = 16 SM-cyc crossbar vs 32 FFMA2 = 16 SM-cyc fma).
// Each warp alone on an SMSP saturates its fma pipe (64 cyc/k >= 44 instr).
// Grid (8 n-tiles, 24 m-tiles) = 192 CTAs. Double-buffered smem.
// ---------------------------------------------------------------------------
__global__ __launch_bounds__(64) void gemm_kernel(
    const float* __restrict__ z_t, const float* __restrict__ z_o,
    const float* __restrict__ W1,  const float* __restrict__ b1)
{
    __shared__ float As[2][16][68];   // [buf][k][m]; 272B row (16B mult)
    __shared__ float Bs[2][16][68];   // [buf][k][n]; 272B row (16B mult)

    const int tid = threadIdx.x;
    const int mt  = blockIdx.y;             // 0..23
    const int n0  = blockIdx.x << 6;        // 0..448
    const bool isHo = (mt >= 16);
    const int m0 = (isHo ? (mt - 16) : mt) << 6;
    const float* A = isHo ? z_o : z_t;
    const float* B = isHo ? (W1 + (u64)DD * HH) : W1;
    float* C = isHo ? g_ho : g_ht;

    // A staging: thread = one m row (tid), 4 float4 along k (16 k)
    // B staging: k row = tid>>2 (0..15), n base = (tid&3)*16, 4 float4
    const int bk  = tid >> 2;
    const int bn4 = (tid & 3) << 4;

    // compute: m oct at ty*8, n oct at tx*8
    const int tx = tid & 7;
    const int ty = tid >> 3;                // 0..7

    u64 acc[8][4];                          // [m][n-pair]
    #pragma unroll
    for (int m = 0; m < 8; m++)
        #pragma unroll
        for (int j = 0; j < 4; j++) acc[m][j] = 0ull;

    const float* aptr = &A[(u64)(m0 + tid) * DD];
    const float* bptr = &B[(u64)bk * HH + n0 + bn4];

    float4 va[4], vb[4];

    // ---- prologue: stage 0 ----
    #pragma unroll
    for (int q = 0; q < 4; q++)
        va[q] = *reinterpret_cast<const float4*>(aptr + (q << 2));
    #pragma unroll
    for (int q = 0; q < 4; q++)
        vb[q] = *reinterpret_cast<const float4*>(bptr + (q << 2));

    #pragma unroll
    for (int q = 0; q < 4; q++) {
        As[0][(q << 2) + 0][tid] = va[q].x;
        As[0][(q << 2) + 1][tid] = va[q].y;
        As[0][(q << 2) + 2][tid] = va[q].z;
        As[0][(q << 2) + 3][tid] = va[q].w;
    }
    #pragma unroll
    for (int q = 0; q < 4; q++)
        *reinterpret_cast<float4*>(&Bs[0][bk][bn4 + (q << 2)]) = vb[q];
    __syncthreads();

    #pragma unroll 1
    for (int kb = 0; kb < 16; kb++) {
        const int cur = kb & 1, nxt = cur ^ 1;

        if (kb < 15) {   // next stage's global loads, hidden under compute
            const float* ap = aptr + ((kb + 1) << 4);
            #pragma unroll
            for (int q = 0; q < 4; q++)
                va[q] = *reinterpret_cast<const float4*>(ap + (q << 2));
            const float* bp = bptr + (u64)((kb + 1) << 4) * HH;
            #pragma unroll
            for (int q = 0; q < 4; q++)
                vb[q] = *reinterpret_cast<const float4*>(bp + (q << 2));
        }

        #pragma unroll
        for (int k = 0; k < 16; k++) {
            float4 af0 = *reinterpret_cast<const float4*>(&As[cur][k][ty << 3]);
            float4 af1 = *reinterpret_cast<const float4*>(&As[cur][k][(ty << 3) + 4]);
            ulonglong2 b01 = *reinterpret_cast<const ulonglong2*>(&Bs[cur][k][tx << 3]);
            ulonglong2 b23 = *reinterpret_cast<const ulonglong2*>(&Bs[cur][k][(tx << 3) + 4]);
            u64 ad[8];
            ad[0] = dup2(af0.x); ad[1] = dup2(af0.y);
            ad[2] = dup2(af0.z); ad[3] = dup2(af0.w);
            ad[4] = dup2(af1.x); ad[5] = dup2(af1.y);
            ad[6] = dup2(af1.z); ad[7] = dup2(af1.w);
            #pragma unroll
            for (int m = 0; m < 8; m++) {
                acc[m][0] = fma2(ad[m], b01.x, acc[m][0]);
                acc[m][1] = fma2(ad[m], b01.y, acc[m][1]);
                acc[m][2] = fma2(ad[m], b23.x, acc[m][2]);
                acc[m][3] = fma2(ad[m], b23.y, acc[m][3]);
            }
        }

        if (kb < 15) {   // store into the other buffer, then sync
            #pragma unroll
            for (int q = 0; q < 4; q++) {
                As[nxt][(q << 2) + 0][tid] = va[q].x;
                As[nxt][(q << 2) + 1][tid] = va[q].y;
                As[nxt][(q << 2) + 2][tid] = va[q].z;
                As[nxt][(q << 2) + 3][tid] = va[q].w;
            }
            #pragma unroll
            for (int q = 0; q < 4; q++)
                *reinterpret_cast<float4*>(&Bs[nxt][bk][bn4 + (q << 2)]) = vb[q];
            __syncthreads();
        }
    }

    // epilogue: thread's n range contiguous: n0 + tx*8 .. +7
    float4 bvA = make_float4(0.f, 0.f, 0.f, 0.f);
    float4 bvB = make_float4(0.f, 0.f, 0.f, 0.f);
    if (isHo) {
        bvA = *reinterpret_cast<const float4*>(&b1[n0 + (tx << 3)]);
        bvB = *reinterpret_cast<const float4*>(&b1[n0 + (tx << 3) + 4]);
    }

    #pragma unroll
    for (int m = 0; m < 8; m++) {
        float2 p0 = *reinterpret_cast<float2*>(&acc[m][0]);
        float2 p1 = *reinterpret_cast<float2*>(&acc[m][1]);
        float2 p2 = *reinterpret_cast<float2*>(&acc[m][2]);
        float2 p3 = *reinterpret_cast<float2*>(&acc[m][3]);
        float4 r0 = make_float4(p0.x + bvA.x, p0.y + bvA.y, p1.x + bvA.z, p1.y + bvA.w);
        float4 r1 = make_float4(p2.x + bvB.x, p2.y + bvB.y, p3.x + bvB.z, p3.y + bvB.w);
        int r = m0 + (ty << 3) + m;
        *reinterpret_cast<float4*>(&C[(u64)r * HH + n0 + (tx << 3)])     = r0;
        *reinterpret_cast<float4*>(&C[(u64)r * HH + n0 + (tx << 3) + 4]) = r1;
    }
}

// ---------------------------------------------------------------------------
// Per-row linear terms: ct[t] = 0.505*<ht[t],W2>, co[o] = 0.505*<ho[o],W2>+b2
// ---------------------------------------------------------------------------
__global__ __launch_bounds__(256) void reduce_kernel(
    const float* __restrict__ W2, const float* __restrict__ b2)
{
    int warp = (blockIdx.x * blockDim.x + threadIdx.x) >> 5;
    int lane = threadIdx.x & 31;
    const float* row;
    float* dst;
    float extra = 0.f;
    if (warp < TT) { row = g_ht + (u64)warp * HH; dst = g_ct + warp; }
    else { row = g_ho + (u64)(warp - TT) * HH; dst = g_co + (warp - TT); extra = b2[0]; }
    float s = 0.f;
    #pragma unroll
    for (int i = 0; i < 4; i++) {
        float4 v = *reinterpret_cast<const float4*>(&row[(lane + 32 * i) << 2]);
        float4 w = *reinterpret_cast<const float4*>(&W2[(lane + 32 * i) << 2]);
        s += v.x * w.x + v.y * w.y + v.z * w.z + v.w * w.w;
    }
    #pragma unroll
    for (int off = 16; off; off >>= 1) s += __shfl_xor_sync(0xffffffffu, s, off);
    if (lane == 0) *dst = 0.505f * s + extra;
}

// ---------------------------------------------------------------------------
// Pairwise kernel: out[t,o] = ct[t]+co[o] + sum_h |ht+ho| * (0.495*W2[h])
// 32x32 tile, 64 threads, grid 512 CTAs (~3.5 CTAs/SM, ~7 warps/SM),
// micro 4t x 4o (crossbar 9 loads vs fma/alu 32/32 SM-cyc per warp-hq —
// near-balanced). Depth-2 register pipeline over hq.
// ---------------------------------------------------------------------------
__global__ __launch_bounds__(64) void pair_kernel(
    const float* __restrict__ W2, float* __restrict__ out)
{
    __shared__ float4 sA[16][33];      // [hq][t], float4 = 4 h; 528B row
    __shared__ float4 sB[16][33];      // [hq][o]
    __shared__ float4 sW[HH / 4];      // 0.495*W2 quads

    const int tid = threadIdx.x;
    const int tx = tid & 7;            // o lane (o = tx + 8j)
    const int ty = tid >> 3;           // t lane (t = ty + 8i), 0..7
    const int t0 = blockIdx.y << 5;
    const int o0 = blockIdx.x << 5;

    // stage scaled W2 (64 threads x 2 quads)
    {
        float4 w = *reinterpret_cast<const float4*>(&W2[tid << 2]);
        w.x *= 0.495f; w.y *= 0.495f; w.z *= 0.495f; w.w *= 0.495f;
        sW[tid] = w;
        float4 w2 = *reinterpret_cast<const float4*>(&W2[(tid + 64) << 2]);
        w2.x *= 0.495f; w2.y *= 0.495f; w2.z *= 0.495f; w2.w *= 0.495f;
        sW[tid + 64] = w2;
    }

    u64 acc[4][4];
    #pragma unroll
    for (int i = 0; i < 4; i++)
        #pragma unroll
        for (int j = 0; j < 4; j++) acc[i][j] = 0ull;

    const int hs = tid & 15;           // hq for staging
    const int ts = tid >> 4;           // 0..3
    const u64 SMASK = 0x7fffffff7fffffffULL;

    const float* pa = &g_ht[(u64)(t0 + ts) * HH + (hs << 2)];
    const float* pb = &g_ho[(u64)(o0 + ts) * HH + (hs << 2)];

    #pragma unroll 1
    for (int c = 0; c < 8; c++) {      // 8 chunks of 64 h
        __syncthreads();
        #pragma unroll
        for (int r = 0; r < 8; r++)
            sA[hs][ts + (r << 2)] =
                *reinterpret_cast<const float4*>(pa + (c << 6) + (u64)(r << 2) * HH);
        #pragma unroll
        for (int r = 0; r < 8; r++)
            sB[hs][ts + (r << 2)] =
                *reinterpret_cast<const float4*>(pb + (c << 6) + (u64)(r << 2) * HH);
        __syncthreads();

        // ---- depth-2 pipelined hq loop ----
        ulonglong2 w = *reinterpret_cast<const ulonglong2*>(&sW[c << 4]);
        ulonglong2 a[4], b[4];
        #pragma unroll
        for (int i = 0; i < 4; i++)
            a[i] = *reinterpret_cast<const ulonglong2*>(&sA[0][ty + (i << 3)]);
        #pragma unroll
        for (int j = 0; j < 4; j++)
            b[j] = *reinterpret_cast<const ulonglong2*>(&sB[0][tx + (j << 3)]);

        #pragma unroll
        for (int hq = 0; hq < 16; hq++) {
            ulonglong2 wn, an[4], bn[4];
            if (hq < 15) {
                wn = *reinterpret_cast<const ulonglong2*>(&sW[(c << 4) + hq + 1]);
                #pragma unroll
                for (int i = 0; i < 4; i++)
                    an[i] = *reinterpret_cast<const ulonglong2*>(&sA[hq + 1][ty + (i << 3)]);
                #pragma unroll
                for (int j = 0; j < 4; j++)
                    bn[j] = *reinterpret_cast<const ulonglong2*>(&sB[hq + 1][tx + (j << 3)]);
            }

            #pragma unroll
            for (int i = 0; i < 4; i++)
                #pragma unroll
                for (int j = 0; j < 4; j++) {
                    u64 x = add2(a[i].x, b[j].x) & SMASK;
                    acc[i][j] = fma2(x, w.x, acc[i][j]);
                    u64 y = add2(a[i].y, b[j].y) & SMASK;
                    acc[i][j] = fma2(y, w.y, acc[i][j]);
                }

            if (hq < 15) {
                w = wn;
                #pragma unroll
                for (int i = 0; i < 4; i++) a[i] = an[i];
                #pragma unroll
                for (int j = 0; j < 4; j++) b[j] = bn[j];
            }
        }
    }

    float ctv[4], cov[4];
    #pragma unroll
    for (int i = 0; i < 4; i++) ctv[i] = g_ct[t0 + ty + (i << 3)];
    #pragma unroll
    for (int j = 0; j < 4; j++) cov[j] = g_co[o0 + tx + (j << 3)];
    #pragma unroll
    for (int i = 0; i < 4; i++)
        #pragma unroll
        for (int j = 0; j < 4; j++) {
            float2 p = *reinterpret_cast<float2*>(&acc[i][j]);
            out[(u64)(t0 + ty + (i << 3)) * OO + o0 + tx + (j << 3)]
                = ctv[i] + cov[j] + p.x + p.y;
        }
}

extern "C" void kernel_launch(void* const* d_in, const int* in_sizes, int n_in,
                              void* d_out, int out_size)
{
    const float* z_t = (const float*)d_in[0];   // [1024,256]
    const float* z_o = (const float*)d_in[1];   // [512,256]
    const float* W1  = (const float*)d_in[2];   // [512,512]
    const float* b1  = (const float*)d_in[3];   // [512]
    const float* W2  = (const float*)d_in[4];   // [512,1]
    const float* b2  = (const float*)d_in[5];   // [1]
    float* out = (float*)d_out;                 // [1024,512]

    gemm_kernel<<<dim3(8, 24), 64>>>(z_t, z_o, W1, b1);
    reduce_kernel<<<192, 256>>>(W2, b2);
    pair_kernel<<<dim3(OO / 32, TT / 32), 64>>>(W2, out);
}